// round 1
// baseline (speedup 1.0000x reference)
#include <cuda_runtime.h>
#include <cuda_bf16.h>
#include <math.h>

// Problem constants
#define BATCH 2
#define SEQ   2048
#define DMODEL 1024
#define NHEAD 16
#define DK    64
#define SCALE 0.35355339059327376f  // 64^-0.25

#define M_TOT (BATCH * SEQ)  // 4096

// Scratch (device globals: allocation-free rule)
__device__ float g_q[BATCH * NHEAD * SEQ * DK];     // [B,H,L,DK], pre-scaled
__device__ float g_k[BATCH * NHEAD * SEQ * DK];     // [B,H,L,DK], pre-scaled
__device__ float g_v[BATCH * NHEAD * SEQ * DK];     // [B,H,L,DK]
__device__ float g_attn[BATCH * SEQ * DMODEL];      // [B,L,D]

// ---------------------------------------------------------------------------
// Projection GEMM: out = X @ W^T  (X: [M, 1024], W: [1024, 1024] row = out feat)
// headMode==1: write out[(b*H+h)*L + l)*DK + dk] * scale   (m=b*L+l, n=h*DK+dk)
// headMode==0: write out[m*1024 + n]
// Tiling: 64x64 block, BK=16, 256 threads, 4x4 micro-tile per thread.
// ---------------------------------------------------------------------------
__global__ __launch_bounds__(256) void proj_kernel(
    const float* __restrict__ X, const float* __restrict__ W,
    float* __restrict__ out, int headMode, float scale)
{
    __shared__ float As[64][17];
    __shared__ float Bs[64][17];

    const int tid = threadIdx.x;
    const int tx = tid & 15;        // 0..15 -> n micro
    const int ty = tid >> 4;        // 0..15 -> m micro
    const int m0 = blockIdx.y * 64;
    const int n0 = blockIdx.x * 64;

    float acc[4][4] = {};

    const int lr = tid >> 4;   // load row base 0..15
    const int lc = tid & 15;   // load col 0..15

    for (int k0 = 0; k0 < DMODEL; k0 += 16) {
#pragma unroll
        for (int p = 0; p < 4; p++) {
            int r = lr + p * 16;
            As[r][lc] = X[(size_t)(m0 + r) * DMODEL + k0 + lc];
            Bs[r][lc] = W[(size_t)(n0 + r) * DMODEL + k0 + lc];
        }
        __syncthreads();
#pragma unroll
        for (int kk = 0; kk < 16; kk++) {
            float a[4], b[4];
#pragma unroll
            for (int i = 0; i < 4; i++) a[i] = As[ty * 4 + i][kk];
#pragma unroll
            for (int j = 0; j < 4; j++) b[j] = Bs[tx * 4 + j][kk];
#pragma unroll
            for (int i = 0; i < 4; i++)
#pragma unroll
                for (int j = 0; j < 4; j++)
                    acc[i][j] = fmaf(a[i], b[j], acc[i][j]);
        }
        __syncthreads();
    }

#pragma unroll
    for (int i = 0; i < 4; i++) {
        int m = m0 + ty * 4 + i;
#pragma unroll
        for (int j = 0; j < 4; j++) {
            int n = n0 + tx * 4 + j;
            float v = acc[i][j] * scale;
            if (headMode) {
                int b = m >> 11;         // m / 2048
                int l = m & 2047;
                int h = n >> 6;          // n / 64
                int dk = n & 63;
                out[((((size_t)b * NHEAD + h) * SEQ + l) << 6) + dk] = v;
            } else {
                out[(size_t)m * DMODEL + n] = v;
            }
        }
    }
}

// ---------------------------------------------------------------------------
// Flash attention per (b,h): 64-query x 64-key tiles, online softmax.
// q/k pre-scaled by dk^-0.25 each. posbias added before softmax.
// grid: (L/64, B*H), 256 threads. Static smem = 48KB exactly.
// ---------------------------------------------------------------------------
__global__ __launch_bounds__(256) void attn_kernel(
    const float* __restrict__ q, const float* __restrict__ k,
    const float* __restrict__ v, const float* __restrict__ pb,
    float* __restrict__ out)
{
    __shared__ float Qs[64 * 64];   // [row][dk], stride 64
    __shared__ float KsT[64 * 64];  // [dk][key], stride 64; reused as P [row][key]
    __shared__ float Vs[64 * 64];   // [key][dk], stride 64

    const int tid = threadIdx.x;
    const int tx = tid & 15;   // key-col group
    const int ty = tid >> 4;   // query-row group
    const int bh = blockIdx.y;             // 0..31
    const int qb = blockIdx.x * 64;        // query tile base

    const float* qg = q + ((size_t)bh * SEQ + qb) * DK;
    const float* kbase = k + (size_t)bh * SEQ * DK;
    const float* vbase = v + (size_t)bh * SEQ * DK;
    const float* pbbase = pb + (size_t)bh * SEQ * SEQ;

    // load Q tile (contiguous 4096 floats)
    {
        const float4* src = (const float4*)qg;
        float4* dst = (float4*)Qs;
        for (int i = tid; i < 1024; i += 256) dst[i] = src[i];
    }

    float mi[4], li[4], o[4][4];
#pragma unroll
    for (int i = 0; i < 4; i++) {
        mi[i] = -INFINITY;
        li[i] = 0.f;
#pragma unroll
        for (int j = 0; j < 4; j++) o[i][j] = 0.f;
    }

    for (int kb = 0; kb < SEQ; kb += 64) {
        // load K tile transposed, V tile direct
        {
            const float4* ks = (const float4*)(kbase + (size_t)kb * DK);
            const float4* vs = (const float4*)(vbase + (size_t)kb * DK);
            float4* vd = (float4*)Vs;
            for (int i = tid; i < 1024; i += 256) {
                float4 t = ks[i];
                int row = i >> 4;           // key index (64 elems = 16 float4 per row)
                int col = (i & 15) << 2;    // dk base
                KsT[(col + 0) * 64 + row] = t.x;
                KsT[(col + 1) * 64 + row] = t.y;
                KsT[(col + 2) * 64 + row] = t.z;
                KsT[(col + 3) * 64 + row] = t.w;
                vd[i] = vs[i];
            }
        }
        __syncthreads();

        // S = Q Kt  (4x4 per thread)
        float acc[4][4] = {};
#pragma unroll
        for (int kk = 0; kk < 64; kk++) {
            float a[4], b[4];
#pragma unroll
            for (int i = 0; i < 4; i++) a[i] = Qs[(ty * 4 + i) * 64 + kk];
#pragma unroll
            for (int j = 0; j < 4; j++) b[j] = KsT[kk * 64 + tx * 4 + j];
#pragma unroll
            for (int i = 0; i < 4; i++)
#pragma unroll
                for (int j = 0; j < 4; j++)
                    acc[i][j] = fmaf(a[i], b[j], acc[i][j]);
        }

        // add posbias (coalesced float4 per row)
#pragma unroll
        for (int i = 0; i < 4; i++) {
            const float* row = pbbase + (size_t)(qb + ty * 4 + i) * SEQ + kb;
            float4 pv = *(const float4*)(row + tx * 4);
            acc[i][0] += pv.x; acc[i][1] += pv.y;
            acc[i][2] += pv.z; acc[i][3] += pv.w;
        }

        // online softmax update (rows owned by 16 tx lanes; reduce via shfl)
#pragma unroll
        for (int i = 0; i < 4; i++) {
            float mr = fmaxf(fmaxf(acc[i][0], acc[i][1]),
                             fmaxf(acc[i][2], acc[i][3]));
            mr = fmaxf(mr, __shfl_xor_sync(0xffffffffu, mr, 8));
            mr = fmaxf(mr, __shfl_xor_sync(0xffffffffu, mr, 4));
            mr = fmaxf(mr, __shfl_xor_sync(0xffffffffu, mr, 2));
            mr = fmaxf(mr, __shfl_xor_sync(0xffffffffu, mr, 1));
            float mn = fmaxf(mi[i], mr);
            float al = __expf(mi[i] - mn);
            float rs = 0.f;
#pragma unroll
            for (int j = 0; j < 4; j++) {
                acc[i][j] = __expf(acc[i][j] - mn);
                rs += acc[i][j];
            }
            rs += __shfl_xor_sync(0xffffffffu, rs, 8);
            rs += __shfl_xor_sync(0xffffffffu, rs, 4);
            rs += __shfl_xor_sync(0xffffffffu, rs, 2);
            rs += __shfl_xor_sync(0xffffffffu, rs, 1);
            li[i] = li[i] * al + rs;
            mi[i] = mn;
#pragma unroll
            for (int j = 0; j < 4; j++) o[i][j] *= al;
        }

        __syncthreads();   // everyone done reading KsT (S loop)
        // write P into KsT buffer: P[row][key]
#pragma unroll
        for (int i = 0; i < 4; i++)
#pragma unroll
            for (int j = 0; j < 4; j++)
                KsT[(ty * 4 + i) * 64 + tx * 4 + j] = acc[i][j];
        __syncthreads();

        // O += P @ V
#pragma unroll
        for (int n = 0; n < 64; n++) {
            float a[4], b[4];
#pragma unroll
            for (int i = 0; i < 4; i++) a[i] = KsT[(ty * 4 + i) * 64 + n];
#pragma unroll
            for (int j = 0; j < 4; j++) b[j] = Vs[n * 64 + tx * 4 + j];
#pragma unroll
            for (int i = 0; i < 4; i++)
#pragma unroll
                for (int j = 0; j < 4; j++)
                    o[i][j] = fmaf(a[i], b[j], o[i][j]);
        }
        __syncthreads();   // before next tile overwrites KsT/Vs
    }

    // write normalized output into [B, L, D] layout
    const int b = bh >> 4;      // bh / 16
    const int h = bh & 15;
#pragma unroll
    for (int i = 0; i < 4; i++) {
        int l = qb + ty * 4 + i;
        float inv = 1.f / li[i];
        float* dst = out + ((size_t)b * SEQ + l) * DMODEL + h * DK + tx * 4;
        float4 w;
        w.x = o[i][0] * inv; w.y = o[i][1] * inv;
        w.z = o[i][2] * inv; w.w = o[i][3] * inv;
        *(float4*)dst = w;
    }
}

// ---------------------------------------------------------------------------
// Launch
// ---------------------------------------------------------------------------
extern "C" void kernel_launch(void* const* d_in, const int* in_sizes, int n_in,
                              void* d_out, int out_size)
{
    const float* query = (const float*)d_in[0];
    const float* key   = (const float*)d_in[1];
    const float* value = (const float*)d_in[2];
    const float* pbias = (const float*)d_in[3];
    const float* Wq    = (const float*)d_in[4];
    const float* Wk    = (const float*)d_in[5];
    const float* Wv    = (const float*)d_in[6];
    const float* Wo    = (const float*)d_in[7];
    float* out = (float*)d_out;

    float *qp, *kp, *vp, *ap;
    cudaGetSymbolAddress((void**)&qp, g_q);
    cudaGetSymbolAddress((void**)&kp, g_k);
    cudaGetSymbolAddress((void**)&vp, g_v);
    cudaGetSymbolAddress((void**)&ap, g_attn);

    dim3 pgrid(DMODEL / 64, M_TOT / 64);   // (16, 64)
    proj_kernel<<<pgrid, 256>>>(query, Wq, qp, 1, SCALE);
    proj_kernel<<<pgrid, 256>>>(key,   Wk, kp, 1, SCALE);
    proj_kernel<<<pgrid, 256>>>(value, Wv, vp, 1, 1.0f);

    dim3 agrid(SEQ / 64, BATCH * NHEAD);   // (32, 32)
    attn_kernel<<<agrid, 256>>>(qp, kp, vp, pbias, ap);

    proj_kernel<<<pgrid, 256>>>(ap, Wo, out, 0, 1.0f);
}

// round 2
// speedup vs baseline: 3.4354x; 3.4354x over previous
#include <cuda_runtime.h>
#include <cuda_bf16.h>
#include <math.h>
#include <stdint.h>

// Problem constants
#define BATCH 2
#define SEQ   2048
#define DMODEL 1024
#define NHEAD 16
#define DK    64
#define SCALE 0.35355339059327376f  // 64^-0.25
#define M_TOT (BATCH * SEQ)         // 4096

// Scratch (device globals: allocation-free rule)
__device__ float g_q[BATCH * NHEAD * SEQ * DK];   // [B,H,L,DK] pre-scaled
__device__ float g_k[BATCH * NHEAD * SEQ * DK];   // [B,H,L,DK] pre-scaled
__device__ float g_v[BATCH * NHEAD * SEQ * DK];   // [B,H,L,DK]
__device__ float g_attn[BATCH * SEQ * DMODEL];    // [B,L,D]

__device__ __forceinline__ uint32_t f2tf(float f) {
    uint32_t u;
    asm("cvt.rna.tf32.f32 %0, %1;" : "=r"(u) : "f"(f));
    return u;
}

__device__ __forceinline__ void mma_tf32(float* c, const uint32_t* a, const uint32_t* b) {
    asm volatile(
        "mma.sync.aligned.m16n8k8.row.col.f32.tf32.tf32.f32 "
        "{%0,%1,%2,%3}, {%4,%5,%6,%7}, {%8,%9}, {%0,%1,%2,%3};\n"
        : "+f"(c[0]), "+f"(c[1]), "+f"(c[2]), "+f"(c[3])
        : "r"(a[0]), "r"(a[1]), "r"(a[2]), "r"(a[3]), "r"(b[0]), "r"(b[1]));
}

// ---------------------------------------------------------------------------
// Projection GEMM (tf32 tensor cores): out = X @ W^T
// X: [M,1024] row-major, W: [1024,1024] row-major (rows = out features, K-major)
// Tile 128x128, BK=32, 256 threads = 8 warps as 4(m) x 2(n), warp tile 32x64.
// headMode==1: out[((b*H+h)*L+l)*DK+dk] = v*scale  (m=b*L+l, n=h*DK+dk)
// headMode==0: out[m*1024+n] = v
// ---------------------------------------------------------------------------
#define PPAD 36
__global__ __launch_bounds__(256) void proj_tf32(
    const float* __restrict__ X, const float* __restrict__ W,
    float* __restrict__ out, int headMode, float scale)
{
    __shared__ uint32_t As[128 * PPAD];
    __shared__ uint32_t Bs[128 * PPAD];

    const int tid = threadIdx.x;
    const int lane = tid & 31;
    const int warp = tid >> 5;
    const int wm = warp >> 1;         // 0..3
    const int wn = warp & 1;          // 0..1
    const int gr = lane >> 2;         // 0..7
    const int gc = lane & 3;          // 0..3
    const int m0 = blockIdx.y * 128;
    const int n0 = blockIdx.x * 128;

    float acc[2][8][4] = {};

    for (int k0 = 0; k0 < DMODEL; k0 += 32) {
#pragma unroll
        for (int p = 0; p < 4; p++) {
            int idx = tid + 256 * p;          // 0..1023
            int r = idx >> 3;                 // 0..127
            int c = (idx & 7) * 4;            // 0..28
            float4 a = *(const float4*)&X[(size_t)(m0 + r) * DMODEL + k0 + c];
            float4 b = *(const float4*)&W[(size_t)(n0 + r) * DMODEL + k0 + c];
            uint32_t* pa = &As[r * PPAD + c];
            pa[0] = f2tf(a.x); pa[1] = f2tf(a.y); pa[2] = f2tf(a.z); pa[3] = f2tf(a.w);
            uint32_t* pb = &Bs[r * PPAD + c];
            pb[0] = f2tf(b.x); pb[1] = f2tf(b.y); pb[2] = f2tf(b.z); pb[3] = f2tf(b.w);
        }
        __syncthreads();

#pragma unroll
        for (int kk = 0; kk < 32; kk += 8) {
            uint32_t afr[2][4], bfr[8][2];
#pragma unroll
            for (int mt = 0; mt < 2; mt++) {
                int rm = wm * 32 + mt * 16;
                afr[mt][0] = As[(rm + gr) * PPAD + kk + gc];
                afr[mt][1] = As[(rm + 8 + gr) * PPAD + kk + gc];
                afr[mt][2] = As[(rm + gr) * PPAD + kk + 4 + gc];
                afr[mt][3] = As[(rm + 8 + gr) * PPAD + kk + 4 + gc];
            }
#pragma unroll
            for (int nt = 0; nt < 8; nt++) {
                int cn = wn * 64 + nt * 8;
                bfr[nt][0] = Bs[(cn + gr) * PPAD + kk + gc];
                bfr[nt][1] = Bs[(cn + gr) * PPAD + kk + 4 + gc];
            }
#pragma unroll
            for (int mt = 0; mt < 2; mt++)
#pragma unroll
                for (int nt = 0; nt < 8; nt++)
                    mma_tf32(acc[mt][nt], afr[mt], bfr[nt]);
        }
        __syncthreads();
    }

    // epilogue
#pragma unroll
    for (int mt = 0; mt < 2; mt++) {
#pragma unroll
        for (int nt = 0; nt < 8; nt++) {
#pragma unroll
            for (int half = 0; half < 2; half++) {
                int m = m0 + wm * 32 + mt * 16 + gr + half * 8;
                int n = n0 + wn * 64 + nt * 8 + gc * 2;
                float v0 = acc[mt][nt][half * 2 + 0] * scale;
                float v1 = acc[mt][nt][half * 2 + 1] * scale;
                if (headMode) {
                    int b = m >> 11;
                    int l = m & 2047;
                    int h = n >> 6;
                    int dk = n & 63;
                    float* dst = &g_q[0]; // placeholder; use out
                    dst = out + ((((size_t)b * NHEAD + h) * SEQ + l) << 6) + dk;
                    dst[0] = v0; dst[1] = v1;
                } else {
                    float* dst = out + (size_t)m * DMODEL + n;
                    *(float2*)dst = make_float2(v0, v1);
                }
            }
        }
    }
}

// ---------------------------------------------------------------------------
// Flash attention (tf32 tensor cores) per (b,h).
// Block: 64 queries, 128 threads = 4 warps, each warp owns 16 query rows.
// Q fragments live in registers for the whole K loop.
// Smem: KP [64][68] (K tile, then reused for P), VT [64][68] (V transposed).
// ---------------------------------------------------------------------------
#define APAD 68
__global__ __launch_bounds__(128) void attn_tf32(
    const float* __restrict__ q, const float* __restrict__ k,
    const float* __restrict__ v, const float* __restrict__ pb,
    float* __restrict__ out)
{
    __shared__ uint32_t KP[64 * APAD];
    __shared__ uint32_t VT[64 * APAD];

    const int tid = threadIdx.x;
    const int lane = tid & 31;
    const int warp = tid >> 5;        // 0..3
    const int gr = lane >> 2;         // 0..7
    const int gc = lane & 3;          // 0..3
    const int bh = blockIdx.y;        // 0..31
    const int qb = blockIdx.x * 64;

    // Q fragments: [8 k-steps][4 regs], rows warp*16 .. +16
    uint32_t qa[8][4];
    {
        const float* qg = q + ((size_t)bh * SEQ + qb + warp * 16) * DK;
#pragma unroll
        for (int ks = 0; ks < 8; ks++) {
            qa[ks][0] = f2tf(qg[(size_t)gr * DK + ks * 8 + gc]);
            qa[ks][1] = f2tf(qg[(size_t)(gr + 8) * DK + ks * 8 + gc]);
            qa[ks][2] = f2tf(qg[(size_t)gr * DK + ks * 8 + 4 + gc]);
            qa[ks][3] = f2tf(qg[(size_t)(gr + 8) * DK + ks * 8 + 4 + gc]);
        }
    }

    float mrow[2] = {-INFINITY, -INFINITY};
    float lrow[2] = {0.f, 0.f};
    float oacc[8][4] = {};

    const float* kbase = k + (size_t)bh * SEQ * DK;
    const float* vbase = v + (size_t)bh * SEQ * DK;
    const float* pbbase = pb + ((size_t)bh * SEQ + qb + warp * 16) * SEQ;

    for (int kb = 0; kb < SEQ; kb += 64) {
        __syncthreads();   // previous tile fully consumed before overwrite
        {
            const float4* ksrc = (const float4*)(kbase + (size_t)kb * DK);
            const float4* vsrc = (const float4*)(vbase + (size_t)kb * DK);
#pragma unroll
            for (int p = 0; p < 8; p++) {
                int idx = tid + 128 * p;          // 0..1023
                int r = idx >> 4;                 // key 0..63
                int c = (idx & 15) * 4;           // dk 0..60
                float4 t = ksrc[idx];
                uint32_t* d = &KP[r * APAD + c];
                d[0] = f2tf(t.x); d[1] = f2tf(t.y); d[2] = f2tf(t.z); d[3] = f2tf(t.w);
                float4 u = vsrc[idx];
                VT[(c + 0) * APAD + r] = f2tf(u.x);
                VT[(c + 1) * APAD + r] = f2tf(u.y);
                VT[(c + 2) * APAD + r] = f2tf(u.z);
                VT[(c + 3) * APAD + r] = f2tf(u.w);
            }
        }
        __syncthreads();

        // S = Q K^T  (8 key n-tiles)
        float sacc[8][4] = {};
#pragma unroll
        for (int ks = 0; ks < 8; ks++) {
#pragma unroll
            for (int nt = 0; nt < 8; nt++) {
                uint32_t bfr[2];
                bfr[0] = KP[(nt * 8 + gr) * APAD + ks * 8 + gc];
                bfr[1] = KP[(nt * 8 + gr) * APAD + ks * 8 + 4 + gc];
                mma_tf32(sacc[nt], qa[ks], bfr);
            }
        }
        __syncthreads();   // all warps done reading K tile (KP becomes P buffer)

        // add posbias
#pragma unroll
        for (int nt = 0; nt < 8; nt++) {
            float2 p0 = *(const float2*)&pbbase[(size_t)gr * SEQ + kb + nt * 8 + gc * 2];
            float2 p1 = *(const float2*)&pbbase[(size_t)(gr + 8) * SEQ + kb + nt * 8 + gc * 2];
            sacc[nt][0] += p0.x; sacc[nt][1] += p0.y;
            sacc[nt][2] += p1.x; sacc[nt][3] += p1.y;
        }

        // online softmax (rows r = gr, gr+8; 4 lanes per row share via shfl 1,2)
#pragma unroll
        for (int r = 0; r < 2; r++) {
            float mx = -INFINITY;
#pragma unroll
            for (int nt = 0; nt < 8; nt++)
                mx = fmaxf(mx, fmaxf(sacc[nt][r * 2], sacc[nt][r * 2 + 1]));
            mx = fmaxf(mx, __shfl_xor_sync(0xffffffffu, mx, 1));
            mx = fmaxf(mx, __shfl_xor_sync(0xffffffffu, mx, 2));
            float mn = fmaxf(mrow[r], mx);
            float al = __expf(mrow[r] - mn);
            float rs = 0.f;
#pragma unroll
            for (int nt = 0; nt < 8; nt++) {
                sacc[nt][r * 2]     = __expf(sacc[nt][r * 2] - mn);
                sacc[nt][r * 2 + 1] = __expf(sacc[nt][r * 2 + 1] - mn);
                rs += sacc[nt][r * 2] + sacc[nt][r * 2 + 1];
            }
            rs += __shfl_xor_sync(0xffffffffu, rs, 1);
            rs += __shfl_xor_sync(0xffffffffu, rs, 2);
            lrow[r] = lrow[r] * al + rs;
            mrow[r] = mn;
#pragma unroll
            for (int dt = 0; dt < 8; dt++) {
                oacc[dt][r * 2]     *= al;
                oacc[dt][r * 2 + 1] *= al;
            }
        }

        // write P into KP (own warp rows only -> warp-local dependency)
        {
            int rm = warp * 16;
#pragma unroll
            for (int nt = 0; nt < 8; nt++) {
                uint2 w0 = make_uint2(f2tf(sacc[nt][0]), f2tf(sacc[nt][1]));
                uint2 w1 = make_uint2(f2tf(sacc[nt][2]), f2tf(sacc[nt][3]));
                *(uint2*)&KP[(rm + gr) * APAD + nt * 8 + gc * 2] = w0;
                *(uint2*)&KP[(rm + 8 + gr) * APAD + nt * 8 + gc * 2] = w1;
            }
        }
        __syncwarp();

        // O += P @ V  (contraction over 64 keys)
#pragma unroll
        for (int ks = 0; ks < 8; ks++) {
            uint32_t pa[4];
            int rm = warp * 16;
            pa[0] = KP[(rm + gr) * APAD + ks * 8 + gc];
            pa[1] = KP[(rm + 8 + gr) * APAD + ks * 8 + gc];
            pa[2] = KP[(rm + gr) * APAD + ks * 8 + 4 + gc];
            pa[3] = KP[(rm + 8 + gr) * APAD + ks * 8 + 4 + gc];
#pragma unroll
            for (int dt = 0; dt < 8; dt++) {
                uint32_t bfr[2];
                bfr[0] = VT[(dt * 8 + gr) * APAD + ks * 8 + gc];
                bfr[1] = VT[(dt * 8 + gr) * APAD + ks * 8 + 4 + gc];
                mma_tf32(oacc[dt], pa, bfr);
            }
        }
    }

    // write normalized output into [B, L, D]
    const int b = bh >> 4;
    const int h = bh & 15;
    float inv0 = 1.f / lrow[0];
    float inv1 = 1.f / lrow[1];
    float* dst = out + ((size_t)b * SEQ + qb + warp * 16) * DMODEL + h * DK;
#pragma unroll
    for (int dt = 0; dt < 8; dt++) {
        *(float2*)&dst[(size_t)gr * DMODEL + dt * 8 + gc * 2] =
            make_float2(oacc[dt][0] * inv0, oacc[dt][1] * inv0);
        *(float2*)&dst[(size_t)(gr + 8) * DMODEL + dt * 8 + gc * 2] =
            make_float2(oacc[dt][2] * inv1, oacc[dt][3] * inv1);
    }
}

// ---------------------------------------------------------------------------
// Launch
// ---------------------------------------------------------------------------
extern "C" void kernel_launch(void* const* d_in, const int* in_sizes, int n_in,
                              void* d_out, int out_size)
{
    const float* query = (const float*)d_in[0];
    const float* key   = (const float*)d_in[1];
    const float* value = (const float*)d_in[2];
    const float* pbias = (const float*)d_in[3];
    const float* Wq    = (const float*)d_in[4];
    const float* Wk    = (const float*)d_in[5];
    const float* Wv    = (const float*)d_in[6];
    const float* Wo    = (const float*)d_in[7];
    float* out = (float*)d_out;

    float *qp, *kp, *vp, *ap;
    cudaGetSymbolAddress((void**)&qp, g_q);
    cudaGetSymbolAddress((void**)&kp, g_k);
    cudaGetSymbolAddress((void**)&vp, g_v);
    cudaGetSymbolAddress((void**)&ap, g_attn);

    dim3 pgrid(DMODEL / 128, M_TOT / 128);   // (8, 32)
    proj_tf32<<<pgrid, 256>>>(query, Wq, qp, 1, SCALE);
    proj_tf32<<<pgrid, 256>>>(key,   Wk, kp, 1, SCALE);
    proj_tf32<<<pgrid, 256>>>(value, Wv, vp, 1, 1.0f);

    dim3 agrid(SEQ / 64, BATCH * NHEAD);     // (32, 32)
    attn_tf32<<<agrid, 128>>>(qp, kp, vp, pbias, ap);

    proj_tf32<<<pgrid, 256>>>(ap, Wo, out, 0, 1.0f);
}